// round 16
// baseline (speedup 1.0000x reference)
#include <cuda_runtime.h>
#include <cuda_fp16.h>
#include <cstdint>

#define NMAX 100000
#define EMAX 1600000
#define GMAX 1024
#define HID  64
#define NFEAT 128

// ---------------- scratch (device globals; no allocation allowed) ------------
__device__ __align__(16) int      g_deg[NMAX];
__device__ __align__(16) float    g_dinv[NMAX];
__device__ __align__(16) int2     g_info[NMAX];      // {edge range offset, edge count}
__device__ __align__(16) int      g_fill[NMAX];
__device__ __align__(16) unsigned g_edge[EMAX];      // packed {src:17, fp16 wnorm:15}
__device__ __align__(16) __half   g_hA[NMAX * HID];  // GEMM output (gather source)
__device__ __align__(16) __half   g_hB[NMAX * HID];  // agg output / GEMM input
__device__ __align__(16) float    g_emb[GMAX * HID];
__device__ int g_total;

// ---------------- setup ------------------------------------------------------
__global__ void count_kernel(const int* __restrict__ ei, int E) {
    int e = blockIdx.x * blockDim.x + threadIdx.x;
    if (e < E) atomicAdd(&g_deg[ei[E + e]], 1);
}

__global__ void alloc_kernel(int n) {
    int i = blockIdx.x * blockDim.x + threadIdx.x;
    if (i < n) {
        int d = g_deg[i];                 // real edge count (self-loop separate)
        g_dinv[i] = rsqrtf((float)(d + 1));
        int2 inf;
        inf.x = atomicAdd(&g_total, d);
        inf.y = d;
        g_info[i] = inf;
    }
}

__global__ void fill_kernel(const int* __restrict__ ei, int E) {
    int e = blockIdx.x * blockDim.x + threadIdx.x;
    if (e >= E) return;
    int s = ei[e];
    int d = ei[E + e];
    int pos = g_info[d].x + atomicAdd(&g_fill[d], 1);
    float w = g_dinv[s] * g_dinv[d];                  // > 0 -> fp16 sign bit 0
    unsigned hb = (unsigned)__half_as_ushort(__float2half_rn(w));
    g_edge[pos] = ((unsigned)s << 15) | (hb & 0x7FFFu);
}

// ---------------- mma helpers -------------------------------------------------
__device__ __forceinline__ unsigned smem_u32(const void* p) {
    return (unsigned)__cvta_generic_to_shared(p);
}
__device__ __forceinline__ void ldsm_x4(unsigned& r0, unsigned& r1, unsigned& r2,
                                        unsigned& r3, unsigned addr) {
    asm volatile("ldmatrix.sync.aligned.m8n8.x4.shared.b16 {%0,%1,%2,%3}, [%4];"
                 : "=r"(r0), "=r"(r1), "=r"(r2), "=r"(r3) : "r"(addr));
}
__device__ __forceinline__ void ldsm_x4_trans(unsigned& r0, unsigned& r1, unsigned& r2,
                                              unsigned& r3, unsigned addr) {
    asm volatile("ldmatrix.sync.aligned.m8n8.x4.trans.shared.b16 {%0,%1,%2,%3}, [%4];"
                 : "=r"(r0), "=r"(r1), "=r"(r2), "=r"(r3) : "r"(addr));
}
__device__ __forceinline__ void mma_16816(float* c, unsigned a0, unsigned a1,
                                          unsigned a2, unsigned a3,
                                          unsigned b0, unsigned b1) {
    asm volatile(
        "mma.sync.aligned.m16n8k16.row.col.f32.f16.f16.f32 "
        "{%0,%1,%2,%3}, {%4,%5,%6,%7}, {%8,%9}, {%0,%1,%2,%3};"
        : "+f"(c[0]), "+f"(c[1]), "+f"(c[2]), "+f"(c[3])
        : "r"(a0), "r"(a1), "r"(a2), "r"(a3), "r"(b0), "r"(b1));
}

// ---------------- GEMM (tensor cores): g_hA(fp16)[n,64] = in[n,K] @ W[K,64] --
// 128-row x 64-col block, 8 warps; warp w owns rows w*16..w*16+15, all 64 cols.
// A row-major fp16 smem (stride K+8), W fp16 smem (stride 72). m16n8k16 HMMA.
// INHALF: input x(fp32 arg) vs g_hB(fp16) — chosen in DEVICE code only
// (host-side __device__ symbol args silently read the host shadow on GB300).
template <int K, int INHALF>
__global__ __launch_bounds__(256) void gemm_kernel(const float* __restrict__ xin,
                                                   const float* __restrict__ W, int n) {
    constexpr int AP = K + 8;
    constexpr int WP = 72;
    extern __shared__ __half sm[];
    __half* As = sm;                          // [128][AP]
    __half* Ws = sm + 128 * AP;               // [K][WP]
    int row0 = blockIdx.x * 128;

    for (int i = threadIdx.x; i < K * 16; i += 256) {
        int r = i >> 4;
        int c = (i & 15) * 4;
        float4 v = ((const float4*)W)[i];
        __half2 h0 = __floats2half2_rn(v.x, v.y);
        __half2 h1 = __floats2half2_rn(v.z, v.w);
        uint2 o;
        o.x = *(unsigned*)&h0;
        o.y = *(unsigned*)&h1;
        *(uint2*)&Ws[r * WP + c] = o;
    }
    if (INHALF) {
        for (int i = threadIdx.x; i < 128 * (K / 4); i += 256) {
            int r = i / (K / 4);
            int c = (i % (K / 4)) * 4;
            int gr = row0 + r;
            uint2 v = make_uint2(0u, 0u);
            if (gr < n) v = ((const uint2*)g_hB)[gr * (K / 4) + (c >> 2)];
            *(uint2*)&As[r * AP + c] = v;
        }
    } else {
        for (int i = threadIdx.x; i < 128 * (K / 4); i += 256) {
            int r = i / (K / 4);
            int c = (i % (K / 4)) * 4;
            int gr = row0 + r;
            float4 v = make_float4(0.f, 0.f, 0.f, 0.f);
            if (gr < n) v = ((const float4*)xin)[gr * (K / 4) + (c >> 2)];
            __half2 h0 = __floats2half2_rn(v.x, v.y);
            __half2 h1 = __floats2half2_rn(v.z, v.w);
            uint2 o;
            o.x = *(unsigned*)&h0;
            o.y = *(unsigned*)&h1;
            *(uint2*)&As[r * AP + c] = o;
        }
    }
    __syncthreads();

    int warp = threadIdx.x >> 5;
    int lane = threadIdx.x & 31;
    int m0 = warp * 16;
    int gidx = lane & 7;
    int grp  = lane >> 3;

    int a_row  = m0 + gidx + ((grp & 1) << 3);
    int a_colh = (grp >> 1) << 3;
    unsigned a_base = smem_u32(&As[a_row * AP + a_colh]);
    int b_krow = gidx + ((grp & 1) << 3);
    int b_coln = (grp >> 1) << 3;
    unsigned b_base = smem_u32(&Ws[b_krow * WP + b_coln]);

    float acc[8][4];
#pragma unroll
    for (int t = 0; t < 8; t++) {
#pragma unroll
        for (int j = 0; j < 4; j++) acc[t][j] = 0.f;
    }

#pragma unroll
    for (int k = 0; k < K; k += 16) {
        unsigned a0, a1, a2, a3;
        ldsm_x4(a0, a1, a2, a3, a_base + k * 2);
#pragma unroll
        for (int t = 0; t < 4; t++) {
            unsigned b0, b1, b2, b3;
            ldsm_x4_trans(b0, b1, b2, b3, b_base + (k * WP + t * 16) * 2);
            mma_16816(acc[2 * t],     a0, a1, a2, a3, b0, b1);
            mma_16816(acc[2 * t + 1], a0, a1, a2, a3, b2, b3);
        }
    }

    int cr = lane >> 2;
    int cc = (lane & 3) * 2;
    int gr0 = row0 + m0 + cr;
    int gr1 = gr0 + 8;
#pragma unroll
    for (int t = 0; t < 8; t++) {
        if (gr0 < n) {
            __half2 h = __floats2half2_rn(acc[t][0], acc[t][1]);
            *(unsigned*)&g_hA[gr0 * HID + t * 8 + cc] = *(unsigned*)&h;
        }
        if (gr1 < n) {
            __half2 h = __floats2half2_rn(acc[t][2], acc[t][3]);
            *(unsigned*)&g_hA[gr1 * HID + t * 8 + cc] = *(unsigned*)&h;
        }
    }
}

// ---------------- aggregation ------------------------------------------------
// QUARTER-warp per dst node (warp covers 4 nodes). 8 lanes x uint4 (16B) =
// full 64-dim fp16 row per gather -> LDG.128. One LDG.32 per iteration loads
// 8 edge metas per quarter (32/warp); metas distributed via shfl. Invalid
// edges padded with meta=0 (w=0, src=0: safe). fp32 accumulation.
// FUSEPOOL: accumulate into per-graph embedding (layer 3).
template <int FUSEPOOL>
__global__ __launch_bounds__(256) void agg_kernel(const float* __restrict__ bias,
                                                  const int* __restrict__ batch,
                                                  int n, int relu) {
    int warp = (blockIdx.x * blockDim.x + threadIdx.x) >> 5;
    int lane = threadIdx.x & 31;
    int q    = lane >> 3;          // quarter 0..3
    int ql   = lane & 7;           // lane within quarter
    int node = warp * 4 + q;
    bool valid = node < n;
    int nodec = valid ? node : (n - 1);

    const uint4* hv = (const uint4*)g_hA;      // 8 x uint4 per 64-half row
    float a0 = 0.f, a1 = 0.f, a2 = 0.f, a3 = 0.f;
    float a4 = 0.f, a5 = 0.f, a6 = 0.f, a7 = 0.f;

    int2 inf = g_info[nodec];
    int beg = inf.x;
    int cnt = valid ? inf.y : 0;

    int iters = (cnt + 7) >> 3;
    int maxit = __reduce_max_sync(0xffffffffu, iters);

    for (int it = 0; it < maxit; it++) {
        int ei = it * 8 + ql;
        unsigned meta = (ei < cnt) ? g_edge[beg + ei] : 0u;   // 0 -> w=0, src=0
#pragma unroll
        for (int j = 0; j < 8; j++) {
            unsigned m = __shfl_sync(0xffffffffu, meta, (q << 3) + j);
            float w = __half2float(__ushort_as_half((unsigned short)(m & 0x7FFFu)));
            uint4 u = hv[(m >> 15) * 8 + ql];
            float2 f0 = __half22float2(*(__half2*)&u.x);
            float2 f1 = __half22float2(*(__half2*)&u.y);
            float2 f2 = __half22float2(*(__half2*)&u.z);
            float2 f3 = __half22float2(*(__half2*)&u.w);
            a0 = fmaf(w, f0.x, a0); a1 = fmaf(w, f0.y, a1);
            a2 = fmaf(w, f1.x, a2); a3 = fmaf(w, f1.y, a3);
            a4 = fmaf(w, f2.x, a4); a5 = fmaf(w, f2.y, a5);
            a6 = fmaf(w, f3.x, a6); a7 = fmaf(w, f3.y, a7);
        }
    }

    // self loop + bias (+ relu)
    float di = g_dinv[nodec];
    float sw = di * di;
    uint4 us = hv[nodec * 8 + ql];
    float2 s0 = __half22float2(*(__half2*)&us.x);
    float2 s1 = __half22float2(*(__half2*)&us.y);
    float2 s2 = __half22float2(*(__half2*)&us.z);
    float2 s3 = __half22float2(*(__half2*)&us.w);
    float4 b0 = ((const float4*)bias)[ql * 2];
    float4 b1 = ((const float4*)bias)[ql * 2 + 1];
    a0 = fmaf(sw, s0.x, a0) + b0.x;
    a1 = fmaf(sw, s0.y, a1) + b0.y;
    a2 = fmaf(sw, s1.x, a2) + b0.z;
    a3 = fmaf(sw, s1.y, a3) + b0.w;
    a4 = fmaf(sw, s2.x, a4) + b1.x;
    a5 = fmaf(sw, s2.y, a5) + b1.y;
    a6 = fmaf(sw, s3.x, a6) + b1.z;
    a7 = fmaf(sw, s3.y, a7) + b1.w;
    if (relu) {
        a0 = fmaxf(a0, 0.f); a1 = fmaxf(a1, 0.f);
        a2 = fmaxf(a2, 0.f); a3 = fmaxf(a3, 0.f);
        a4 = fmaxf(a4, 0.f); a5 = fmaxf(a5, 0.f);
        a6 = fmaxf(a6, 0.f); a7 = fmaxf(a7, 0.f);
    }
    if (!valid) return;
    if (FUSEPOOL) {
        int g = batch[node];
        float* dst = &g_emb[g * HID + ql * 8];
        atomicAdd(dst + 0, a0);
        atomicAdd(dst + 1, a1);
        atomicAdd(dst + 2, a2);
        atomicAdd(dst + 3, a3);
        atomicAdd(dst + 4, a4);
        atomicAdd(dst + 5, a5);
        atomicAdd(dst + 6, a6);
        atomicAdd(dst + 7, a7);
    } else {
        __half2 h0 = __floats2half2_rn(a0, a1);
        __half2 h1 = __floats2half2_rn(a2, a3);
        __half2 h2 = __floats2half2_rn(a4, a5);
        __half2 h3 = __floats2half2_rn(a6, a7);
        uint4 o;
        o.x = *(unsigned*)&h0;
        o.y = *(unsigned*)&h1;
        o.z = *(unsigned*)&h2;
        o.w = *(unsigned*)&h3;
        ((uint4*)g_hB)[node * 8 + ql] = o;
    }
}

// ---------------- head: mean + centroid distances, min per class -------------
__global__ void head_kernel(const int* __restrict__ batch, int n,
                            const float* __restrict__ centroids,
                            const float* __restrict__ rbias,
                            float* __restrict__ out) {
    int g = blockIdx.x;
    int t = threadIdx.x;   // 64 threads
    __shared__ float e[HID];
    __shared__ float d[48];
    __shared__ float dpc[16];
    __shared__ float inv_cnt;

    if (t == 0) {
        int lo = 0, hi = n;
        while (lo < hi) { int m = (lo + hi) >> 1; if (batch[m] < g) lo = m + 1; else hi = m; }
        int a = lo;
        lo = 0; hi = n;
        while (lo < hi) { int m = (lo + hi) >> 1; if (batch[m] <= g) lo = m + 1; else hi = m; }
        int c = lo - a;
        inv_cnt = 1.0f / (float)(c > 1 ? c : 1);
    }
    __syncthreads();

    e[t] = g_emb[g * HID + t] * inv_cnt;
    __syncthreads();

    if (t < 48) {
        float acc = 0.f;
#pragma unroll
        for (int k = 0; k < HID; k++) {
            float df = e[k] - centroids[t * HID + k];
            acc = fmaf(df, df, acc);
        }
        d[t] = acc;
    }
    __syncthreads();
    if (t < 16) {
        float m = fminf(d[t * 3], fminf(d[t * 3 + 1], d[t * 3 + 2]));
        dpc[t] = m;
        out[g * 17 + t] = -m;
    }
    __syncthreads();
    if (t == 0) {
        float mm = dpc[0];
#pragma unroll
        for (int i = 1; i < 16; i++) mm = fminf(mm, dpc[i]);
        out[g * 17 + 16] = mm - rbias[0];
    }
}

// ---------------- launch -----------------------------------------------------
extern "C" void kernel_launch(void* const* d_in, const int* in_sizes, int n_in,
                              void* d_out, int out_size) {
    const float* x     = (const float*)d_in[0];
    const int*   ei    = (const int*)d_in[1];
    const int*   batch = (const int*)d_in[2];
    const float* W1    = (const float*)d_in[3];
    const float* b1    = (const float*)d_in[4];
    const float* W2    = (const float*)d_in[5];
    const float* b2    = (const float*)d_in[6];
    const float* W3    = (const float*)d_in[7];
    const float* b3    = (const float*)d_in[8];
    const float* cent  = (const float*)d_in[9];
    const float* rb    = (const float*)d_in[10];
    float* out = (float*)d_out;

    int n = in_sizes[0] / NFEAT;
    int E = in_sizes[1] / 2;
    int G = out_size / 17;

    const int smem128 = (128 * (NFEAT + 8) + NFEAT * 72) * 2;  // 52KB
    const int smem64  = (128 * (HID + 8)  + HID * 72) * 2;     // 27KB

    static cudaStream_t s2;
    static cudaEvent_t ev_fork, ev_csr;
    static void *p_deg, *p_fill, *p_emb, *p_total;
    static int init_done = 0;
    if (!init_done) {
        cudaFuncSetAttribute(gemm_kernel<NFEAT, 0>,
                             cudaFuncAttributeMaxDynamicSharedMemorySize, smem128);
        cudaFuncSetAttribute(gemm_kernel<HID, 1>,
                             cudaFuncAttributeMaxDynamicSharedMemorySize, smem64);
        cudaStreamCreateWithFlags(&s2, cudaStreamNonBlocking);
        cudaEventCreateWithFlags(&ev_fork, cudaEventDisableTiming);
        cudaEventCreateWithFlags(&ev_csr,  cudaEventDisableTiming);
        cudaGetSymbolAddress(&p_deg,   g_deg);
        cudaGetSymbolAddress(&p_fill,  g_fill);
        cudaGetSymbolAddress(&p_emb,   g_emb);
        cudaGetSymbolAddress(&p_total, g_total);
        init_done = 1;
    }

    int gemm_blocks = (n + 127) / 128;
    int agg_blocks  = (n + 31) / 32;   // 8 warps/block, 4 nodes/warp

    // Fork: CSR build on s2 runs concurrently with layer-1 GEMM on stream 0.
    cudaEventRecord(ev_fork, 0);
    cudaStreamWaitEvent(s2, ev_fork, 0);

    cudaMemsetAsync(p_deg,   0, (size_t)n * 4, s2);
    cudaMemsetAsync(p_fill,  0, (size_t)n * 4, s2);
    cudaMemsetAsync(p_total, 0, 4, s2);
    count_kernel<<<(E + 255) / 256, 256, 0, s2>>>(ei, E);
    alloc_kernel<<<(n + 255) / 256, 256, 0, s2>>>(n);
    fill_kernel<<<(E + 255) / 256, 256, 0, s2>>>(ei, E);
    cudaEventRecord(ev_csr, s2);

    // emb zeroing + layer-1 GEMM (x -> A) overlap the CSR build
    cudaMemsetAsync(p_emb, 0, (size_t)G * HID * 4, 0);
    gemm_kernel<NFEAT, 0><<<gemm_blocks, 256, smem128>>>(x, W1, n);

    // join: aggregation needs both the GEMM output and the CSR
    cudaStreamWaitEvent(0, ev_csr, 0);
    agg_kernel<0><<<agg_blocks, 256>>>(b1, batch, n, 1);
    // layer 2
    gemm_kernel<HID, 1><<<gemm_blocks, 256, smem64>>>(nullptr, W2, n);
    agg_kernel<0><<<agg_blocks, 256>>>(b2, batch, n, 1);
    // layer 3 (aggregation fused with mean-pool accumulation)
    gemm_kernel<HID, 1><<<gemm_blocks, 256, smem64>>>(nullptr, W3, n);
    agg_kernel<1><<<agg_blocks, 256>>>(b3, batch, n, 0);

    // head
    head_kernel<<<G, 64>>>(batch, n, cent, rb, out);
}

// round 17
// speedup vs baseline: 1.2062x; 1.2062x over previous
#include <cuda_runtime.h>
#include <cuda_fp16.h>
#include <cstdint>

#define NMAX 100000
#define EMAX 1600000
#define GMAX 1024
#define HID  64
#define NFEAT 128

// ---------------- scratch (device globals; no allocation allowed) ------------
__device__ __align__(16) int      g_deg[NMAX];       // edge count; consumed by fill
__device__ __align__(16) float    g_dinv[NMAX];
__device__ __align__(16) int2     g_info[NMAX];      // {edge range offset, edge count}
__device__ __align__(16) unsigned g_edge[EMAX];      // packed {src:17, fp16 wnorm:15}
__device__ __align__(16) __half   g_hA[NMAX * HID];  // GEMM output (gather source)
__device__ __align__(16) __half   g_hB[NMAX * HID];  // agg output / GEMM input
__device__ int g_total;

// ---------------- setup ------------------------------------------------------
__global__ void count_kernel(const int* __restrict__ ei, int E) {
    int e = blockIdx.x * blockDim.x + threadIdx.x;
    if (e < E) atomicAdd(&g_deg[ei[E + e]], 1);
}

__global__ void alloc_kernel(int n) {
    int i = blockIdx.x * blockDim.x + threadIdx.x;
    if (i < n) {
        int d = g_deg[i];                 // real edge count (self-loop separate)
        g_dinv[i] = rsqrtf((float)(d + 1));
        int2 inf;
        inf.x = atomicAdd(&g_total, d);
        inf.y = d;
        g_info[i] = inf;
    }
}

// slot allocation by decrementing deg (deg is dead after alloc snapshot)
__global__ void fill_kernel(const int* __restrict__ ei, int E) {
    int e = blockIdx.x * blockDim.x + threadIdx.x;
    if (e >= E) return;
    int s = ei[e];
    int d = ei[E + e];
    int slot = atomicSub(&g_deg[d], 1) - 1;           // cnt-1 .. 0
    int pos = g_info[d].x + slot;
    float w = g_dinv[s] * g_dinv[d];                  // > 0 -> fp16 sign bit 0
    unsigned hb = (unsigned)__half_as_ushort(__float2half_rn(w));
    g_edge[pos] = ((unsigned)s << 15) | (hb & 0x7FFFu);
}

// ---------------- mma helpers -------------------------------------------------
__device__ __forceinline__ unsigned smem_u32(const void* p) {
    return (unsigned)__cvta_generic_to_shared(p);
}
__device__ __forceinline__ void ldsm_x4(unsigned& r0, unsigned& r1, unsigned& r2,
                                        unsigned& r3, unsigned addr) {
    asm volatile("ldmatrix.sync.aligned.m8n8.x4.shared.b16 {%0,%1,%2,%3}, [%4];"
                 : "=r"(r0), "=r"(r1), "=r"(r2), "=r"(r3) : "r"(addr));
}
__device__ __forceinline__ void ldsm_x4_trans(unsigned& r0, unsigned& r1, unsigned& r2,
                                              unsigned& r3, unsigned addr) {
    asm volatile("ldmatrix.sync.aligned.m8n8.x4.trans.shared.b16 {%0,%1,%2,%3}, [%4];"
                 : "=r"(r0), "=r"(r1), "=r"(r2), "=r"(r3) : "r"(addr));
}
__device__ __forceinline__ void mma_16816(float* c, unsigned a0, unsigned a1,
                                          unsigned a2, unsigned a3,
                                          unsigned b0, unsigned b1) {
    asm volatile(
        "mma.sync.aligned.m16n8k16.row.col.f32.f16.f16.f32 "
        "{%0,%1,%2,%3}, {%4,%5,%6,%7}, {%8,%9}, {%0,%1,%2,%3};"
        : "+f"(c[0]), "+f"(c[1]), "+f"(c[2]), "+f"(c[3])
        : "r"(a0), "r"(a1), "r"(a2), "r"(a3), "r"(b0), "r"(b1));
}

// ---------------- GEMM (tensor cores): g_hA(fp16)[n,64] = in[n,K] @ W[K,64] --
// 128-row x 64-col block, 8 warps; warp w owns rows w*16..w*16+15, all 64 cols.
// A row-major fp16 smem (stride K+8), W fp16 smem (stride 72). m16n8k16 HMMA.
// INHALF: input x(fp32 arg) vs g_hB(fp16) — chosen in DEVICE code only
// (host-side __device__ symbol args silently read the host shadow on GB300).
template <int K, int INHALF>
__global__ __launch_bounds__(256) void gemm_kernel(const float* __restrict__ xin,
                                                   const float* __restrict__ W, int n) {
    constexpr int AP = K + 8;
    constexpr int WP = 72;
    extern __shared__ __half sm[];
    __half* As = sm;                          // [128][AP]
    __half* Ws = sm + 128 * AP;               // [K][WP]
    int row0 = blockIdx.x * 128;

    for (int i = threadIdx.x; i < K * 16; i += 256) {
        int r = i >> 4;
        int c = (i & 15) * 4;
        float4 v = ((const float4*)W)[i];
        __half2 h0 = __floats2half2_rn(v.x, v.y);
        __half2 h1 = __floats2half2_rn(v.z, v.w);
        uint2 o;
        o.x = *(unsigned*)&h0;
        o.y = *(unsigned*)&h1;
        *(uint2*)&Ws[r * WP + c] = o;
    }
    if (INHALF) {
        for (int i = threadIdx.x; i < 128 * (K / 4); i += 256) {
            int r = i / (K / 4);
            int c = (i % (K / 4)) * 4;
            int gr = row0 + r;
            uint2 v = make_uint2(0u, 0u);
            if (gr < n) v = ((const uint2*)g_hB)[gr * (K / 4) + (c >> 2)];
            *(uint2*)&As[r * AP + c] = v;
        }
    } else {
        for (int i = threadIdx.x; i < 128 * (K / 4); i += 256) {
            int r = i / (K / 4);
            int c = (i % (K / 4)) * 4;
            int gr = row0 + r;
            float4 v = make_float4(0.f, 0.f, 0.f, 0.f);
            if (gr < n) v = ((const float4*)xin)[gr * (K / 4) + (c >> 2)];
            __half2 h0 = __floats2half2_rn(v.x, v.y);
            __half2 h1 = __floats2half2_rn(v.z, v.w);
            uint2 o;
            o.x = *(unsigned*)&h0;
            o.y = *(unsigned*)&h1;
            *(uint2*)&As[r * AP + c] = o;
        }
    }
    __syncthreads();

    int warp = threadIdx.x >> 5;
    int lane = threadIdx.x & 31;
    int m0 = warp * 16;
    int gidx = lane & 7;
    int grp  = lane >> 3;

    int a_row  = m0 + gidx + ((grp & 1) << 3);
    int a_colh = (grp >> 1) << 3;
    unsigned a_base = smem_u32(&As[a_row * AP + a_colh]);
    int b_krow = gidx + ((grp & 1) << 3);
    int b_coln = (grp >> 1) << 3;
    unsigned b_base = smem_u32(&Ws[b_krow * WP + b_coln]);

    float acc[8][4];
#pragma unroll
    for (int t = 0; t < 8; t++) {
#pragma unroll
        for (int j = 0; j < 4; j++) acc[t][j] = 0.f;
    }

#pragma unroll
    for (int k = 0; k < K; k += 16) {
        unsigned a0, a1, a2, a3;
        ldsm_x4(a0, a1, a2, a3, a_base + k * 2);
#pragma unroll
        for (int t = 0; t < 4; t++) {
            unsigned b0, b1, b2, b3;
            ldsm_x4_trans(b0, b1, b2, b3, b_base + (k * WP + t * 16) * 2);
            mma_16816(acc[2 * t],     a0, a1, a2, a3, b0, b1);
            mma_16816(acc[2 * t + 1], a0, a1, a2, a3, b2, b3);
        }
    }

    int cr = lane >> 2;
    int cc = (lane & 3) * 2;
    int gr0 = row0 + m0 + cr;
    int gr1 = gr0 + 8;
#pragma unroll
    for (int t = 0; t < 8; t++) {
        if (gr0 < n) {
            __half2 h = __floats2half2_rn(acc[t][0], acc[t][1]);
            *(unsigned*)&g_hA[gr0 * HID + t * 8 + cc] = *(unsigned*)&h;
        }
        if (gr1 < n) {
            __half2 h = __floats2half2_rn(acc[t][2], acc[t][3]);
            *(unsigned*)&g_hA[gr1 * HID + t * 8 + cc] = *(unsigned*)&h;
        }
    }
}

// ---------------- aggregation (R15 half-warp form) ----------------------------
// Half-warp per dst node (warp covers nodes 2w, 2w+1). 16 lanes x half4 (8B)
// = full 64-dim fp16 row; fp32 accumulation; 8x-unrolled (MLP=8 per half).
// Always writes g_hB (pooling now happens in head via sorted-batch segments).
__global__ __launch_bounds__(256) void agg_kernel(const float* __restrict__ bias,
                                                  int n, int relu) {
    int warp = (blockIdx.x * blockDim.x + threadIdx.x) >> 5;
    int lane = threadIdx.x & 31;
    int half = lane >> 4;
    int sl   = lane & 15;
    int node = warp * 2 + half;
    if (node >= n) return;

    const uint2* hv = (const uint2*)g_hA;     // 8B = 4 halves per lane
    float4 acc = make_float4(0.f, 0.f, 0.f, 0.f);

    int2 inf = g_info[node];
    int beg = inf.x;
    int end = beg + inf.y;
    int e = beg;
    for (; e + 7 < end; e += 8) {
        unsigned p[8];
        uint2 u[8];
#pragma unroll
        for (int j = 0; j < 8; j++) p[j] = g_edge[e + j];
#pragma unroll
        for (int j = 0; j < 8; j++) u[j] = hv[(p[j] >> 15) * 16 + sl];
#pragma unroll
        for (int j = 0; j < 8; j++) {
            float w = __half2float(__ushort_as_half((unsigned short)(p[j] & 0x7FFFu)));
            float2 a = __half22float2(*(__half2*)&u[j].x);
            float2 b = __half22float2(*(__half2*)&u[j].y);
            acc.x = fmaf(w, a.x, acc.x);
            acc.y = fmaf(w, a.y, acc.y);
            acc.z = fmaf(w, b.x, acc.z);
            acc.w = fmaf(w, b.y, acc.w);
        }
    }
    for (; e < end; e++) {
        unsigned p0 = g_edge[e];
        uint2 u0 = hv[(p0 >> 15) * 16 + sl];
        float w0 = __half2float(__ushort_as_half((unsigned short)(p0 & 0x7FFFu)));
        float2 a0 = __half22float2(*(__half2*)&u0.x);
        float2 b0 = __half22float2(*(__half2*)&u0.y);
        acc.x = fmaf(w0, a0.x, acc.x);
        acc.y = fmaf(w0, a0.y, acc.y);
        acc.z = fmaf(w0, b0.x, acc.z);
        acc.w = fmaf(w0, b0.y, acc.w);
    }

    float di = g_dinv[node];
    float sw = di * di;
    uint2 us = hv[node * 16 + sl];
    float2 sa = __half22float2(*(__half2*)&us.x);
    float2 sb = __half22float2(*(__half2*)&us.y);
    float4 b  = ((const float4*)bias)[sl];
    acc.x = fmaf(sw, sa.x, acc.x) + b.x;
    acc.y = fmaf(sw, sa.y, acc.y) + b.y;
    acc.z = fmaf(sw, sb.x, acc.z) + b.z;
    acc.w = fmaf(sw, sb.y, acc.w) + b.w;
    if (relu) {
        acc.x = fmaxf(acc.x, 0.f);
        acc.y = fmaxf(acc.y, 0.f);
        acc.z = fmaxf(acc.z, 0.f);
        acc.w = fmaxf(acc.w, 0.f);
    }
    __half2 h0 = __floats2half2_rn(acc.x, acc.y);
    __half2 h1 = __floats2half2_rn(acc.z, acc.w);
    uint2 o;
    o.x = *(unsigned*)&h0;
    o.y = *(unsigned*)&h1;
    ((uint2*)g_hB)[node * 16 + sl] = o;
}

// ---------------- head: segment mean-pool + centroid distances ---------------
// batch is sorted: graph g's nodes are the contiguous range [a, b) found by
// binary search. Pool = direct streamed sum over that range (no atomics).
__global__ void head_kernel(const int* __restrict__ batch, int n,
                            const float* __restrict__ centroids,
                            const float* __restrict__ rbias,
                            float* __restrict__ out) {
    int g = blockIdx.x;
    int t = threadIdx.x;   // 64 threads
    __shared__ float e[HID];
    __shared__ float d[48];
    __shared__ float dpc[16];
    __shared__ int sa, sb;

    if (t == 0) {
        int lo = 0, hi = n;
        while (lo < hi) { int m = (lo + hi) >> 1; if (batch[m] < g) lo = m + 1; else hi = m; }
        sa = lo;
        lo = 0; hi = n;
        while (lo < hi) { int m = (lo + hi) >> 1; if (batch[m] <= g) lo = m + 1; else hi = m; }
        sb = lo;
    }
    __syncthreads();

    int a = sa, b = sb;
    int c = b - a;
    float inv_cnt = 1.0f / (float)(c > 1 ? c : 1);

    const __half* hb = g_hB;
    float s0 = 0.f, s1 = 0.f, s2 = 0.f, s3 = 0.f;
    int r = a;
    for (; r + 3 < b; r += 4) {
        s0 += __half2float(hb[(r    ) * HID + t]);
        s1 += __half2float(hb[(r + 1) * HID + t]);
        s2 += __half2float(hb[(r + 2) * HID + t]);
        s3 += __half2float(hb[(r + 3) * HID + t]);
    }
    for (; r < b; r++) s0 += __half2float(hb[r * HID + t]);
    e[t] = ((s0 + s1) + (s2 + s3)) * inv_cnt;
    __syncthreads();

    if (t < 48) {
        float acc = 0.f;
#pragma unroll
        for (int k = 0; k < HID; k++) {
            float df = e[k] - centroids[t * HID + k];
            acc = fmaf(df, df, acc);
        }
        d[t] = acc;
    }
    __syncthreads();
    if (t < 16) {
        float m = fminf(d[t * 3], fminf(d[t * 3 + 1], d[t * 3 + 2]));
        dpc[t] = m;
        out[g * 17 + t] = -m;
    }
    __syncthreads();
    if (t == 0) {
        float mm = dpc[0];
#pragma unroll
        for (int i = 1; i < 16; i++) mm = fminf(mm, dpc[i]);
        out[g * 17 + 16] = mm - rbias[0];
    }
}

// ---------------- launch -----------------------------------------------------
extern "C" void kernel_launch(void* const* d_in, const int* in_sizes, int n_in,
                              void* d_out, int out_size) {
    const float* x     = (const float*)d_in[0];
    const int*   ei    = (const int*)d_in[1];
    const int*   batch = (const int*)d_in[2];
    const float* W1    = (const float*)d_in[3];
    const float* b1    = (const float*)d_in[4];
    const float* W2    = (const float*)d_in[5];
    const float* b2    = (const float*)d_in[6];
    const float* W3    = (const float*)d_in[7];
    const float* b3    = (const float*)d_in[8];
    const float* cent  = (const float*)d_in[9];
    const float* rb    = (const float*)d_in[10];
    float* out = (float*)d_out;

    int n = in_sizes[0] / NFEAT;
    int E = in_sizes[1] / 2;
    int G = out_size / 17;

    const int smem128 = (128 * (NFEAT + 8) + NFEAT * 72) * 2;  // 52KB
    const int smem64  = (128 * (HID + 8)  + HID * 72) * 2;     // 27KB

    static cudaStream_t s2;
    static cudaEvent_t ev_fork, ev_csr;
    static void *p_deg, *p_total;
    static int init_done = 0;
    if (!init_done) {
        cudaFuncSetAttribute(gemm_kernel<NFEAT, 0>,
                             cudaFuncAttributeMaxDynamicSharedMemorySize, smem128);
        cudaFuncSetAttribute(gemm_kernel<HID, 1>,
                             cudaFuncAttributeMaxDynamicSharedMemorySize, smem64);
        cudaStreamCreateWithFlags(&s2, cudaStreamNonBlocking);
        cudaEventCreateWithFlags(&ev_fork, cudaEventDisableTiming);
        cudaEventCreateWithFlags(&ev_csr,  cudaEventDisableTiming);
        cudaGetSymbolAddress(&p_deg,   g_deg);
        cudaGetSymbolAddress(&p_total, g_total);
        init_done = 1;
    }

    int gemm_blocks = (n + 127) / 128;
    int agg_blocks  = (n + 15) / 16;   // 8 warps/block, 2 nodes/warp

    // Fork: CSR build on s2 runs concurrently with layer-1 GEMM on stream 0.
    cudaEventRecord(ev_fork, 0);
    cudaStreamWaitEvent(s2, ev_fork, 0);

    cudaMemsetAsync(p_deg,   0, (size_t)n * 4, s2);
    cudaMemsetAsync(p_total, 0, 4, s2);
    count_kernel<<<(E + 255) / 256, 256, 0, s2>>>(ei, E);
    alloc_kernel<<<(n + 255) / 256, 256, 0, s2>>>(n);
    fill_kernel<<<(E + 255) / 256, 256, 0, s2>>>(ei, E);
    cudaEventRecord(ev_csr, s2);

    // layer-1 GEMM (x -> A) overlaps the CSR build
    gemm_kernel<NFEAT, 0><<<gemm_blocks, 256, smem128>>>(x, W1, n);

    // join: aggregation needs both the GEMM output and the CSR
    cudaStreamWaitEvent(0, ev_csr, 0);
    agg_kernel<<<agg_blocks, 256>>>(b1, n, 1);
    // layer 2
    gemm_kernel<HID, 1><<<gemm_blocks, 256, smem64>>>(nullptr, W2, n);
    agg_kernel<<<agg_blocks, 256>>>(b2, n, 1);
    // layer 3
    gemm_kernel<HID, 1><<<gemm_blocks, 256, smem64>>>(nullptr, W3, n);
    agg_kernel<<<agg_blocks, 256>>>(b3, n, 0);

    // head: segment mean-pool (sorted batch) + centroid distances
    head_kernel<<<G, 64>>>(batch, n, cent, rb, out);
}